// round 1
// baseline (speedup 1.0000x reference)
#include <cuda_runtime.h>

#define NB     256
#define NQ     1000
#define NC     81
#define QCN    81000
#define TOPK   100
#define NT     512
#define CAP    4096
#define NSAMP  4096
#define SRANK  64

__device__ __forceinline__ float sigf(float x) {
    return __fdividef(1.0f, 1.0f + __expf(-x));
}

__device__ __forceinline__ void push_cand(unsigned long long key,
                                          unsigned long long* cand, int* cnt) {
    unsigned m = __activemask();
    int lane   = threadIdx.x & 31;
    int leader = __ffs(m) - 1;
    int rank   = __popc(m & ((1u << lane) - 1u));
    int base   = 0;
    if (lane == leader) base = atomicAdd(cnt, __popc(m));
    base = __shfl_sync(m, base, leader);
    int pos = base + rank;
    if (pos < CAP) cand[pos] = key;
}

__global__ __launch_bounds__(NT)
void postprocess_kernel(const float* __restrict__ logits,
                        const float* __restrict__ obj,
                        const float* __restrict__ boxes,
                        const float* __restrict__ unk,
                        const float* __restrict__ tsizes,
                        float* __restrict__ out)
{
    __shared__ unsigned long long s_cand[CAP];   // 32 KB; aliased for samples
    __shared__ float s_w1[NQ];
    __shared__ float s_w2[NQ];
    __shared__ float s_lthr[NQ];
    __shared__ int   s_cnt;

    const int b   = blockIdx.x;
    const int tid = threadIdx.x;
    const float* lg = logits + (size_t)b * QCN;

    // ---- pass 0: per-query weights --------------------------------------
    for (int q = tid; q < NQ; q += NT) {
        float w  = __expf(-obj[b * NQ + q]);
        float su = sigf(unk[b * NQ + q]);
        s_w1[q] = w * (1.0f - su);
        s_w2[q] = w * su;
    }
    __syncthreads();

    // ---- pass 1: stratified sampling (256 q-rows x 16 classes) ----------
    unsigned* s_samp = (unsigned*)s_cand;
    for (int s = tid; s < NSAMP; s += NT) {
        int q = (s >> 4) * 3 + 1;      // 256 distinct queries, spread over [1,766]
        int c = s & 15;                // valid classes 0..15
        float v = s_w1[q] * sigf(lg[q * NC + c]);
        s_samp[s] = __float_as_uint(v);
    }
    __syncthreads();

    // bitonic ascending sort of 4096 u32 sample bits
    for (int k = 2; k <= NSAMP; k <<= 1) {
        for (int j = k >> 1; j > 0; j >>= 1) {
            for (int t = tid; t < NSAMP; t += NT) {
                int x = t ^ j;
                if (x > t) {
                    unsigned a = s_samp[t], bb = s_samp[x];
                    bool up = ((t & k) == 0);
                    if (up ? (a > bb) : (a < bb)) { s_samp[t] = bb; s_samp[x] = a; }
                }
            }
            __syncthreads();
        }
    }
    float thr = __uint_as_float(s_samp[NSAMP - SRANK]);
    __syncthreads();   // everyone has thr before s_cand reuse

    // ---- pass 2: collect candidates (retry loop for safety) -------------
    float curthr = thr;
    int n = 0;
    for (int attempt = 0; attempt < 8; attempt++) {
        float te = curthr * 0.9999f;     // slack: superset is always safe
        for (int q = tid; q < NQ; q += NT) {
            float r = __fdividef(te, s_w1[q]);
            float lt;
            if (r >= 0.999999f) lt = __int_as_float(0x7f800000);  // +inf: none pass
            else lt = __logf(r) - __logf(1.0f - r) - 1e-3f;       // sigmoid^-1 w/ slack
            s_lthr[q] = lt;
        }
        if (tid == 0) s_cnt = 0;
        __syncthreads();

        // class-80 specials
        for (int q = tid; q < NQ; q += NT) {
            if (s_w2[q] >= te) {
                int i = q * NC + 80;
                unsigned long long key =
                    ((unsigned long long)__float_as_uint(s_w2[q]) << 32) |
                    (unsigned)(~(unsigned)i);
                push_cand(key, s_cand, &s_cnt);
            }
        }
        // main scan: load + compare only (no MUFU for non-survivors)
        for (int i = tid; i < QCN; i += NT) {
            unsigned q = (unsigned)i / NC;
            int c = i - (int)q * NC;
            if (c < 60) {
                float v = lg[i];
                if (v >= s_lthr[q]) {
                    float p = s_w1[q] * sigf(v);
                    unsigned long long key =
                        ((unsigned long long)__float_as_uint(p) << 32) |
                        (unsigned)(~(unsigned)i);
                    push_cand(key, s_cand, &s_cnt);
                }
            }
        }
        __syncthreads();
        n = s_cnt;
        if (n >= TOPK && n <= CAP) break;
        if (n < TOPK) curthr *= 0.25f; else curthr *= 4.0f;
        __syncthreads();
    }
    if (n > CAP) n = CAP;

    // ---- pass 3: pad + bitonic sort candidates (ascending) --------------
    for (int t = n + tid; t < CAP; t += NT) s_cand[t] = 0ULL;
    __syncthreads();
    for (int k = 2; k <= CAP; k <<= 1) {
        for (int j = k >> 1; j > 0; j >>= 1) {
            for (int t = tid; t < CAP; t += NT) {
                int x = t ^ j;
                if (x > t) {
                    unsigned long long a = s_cand[t], bb = s_cand[x];
                    bool up = ((t & k) == 0);
                    if (up ? (a > bb) : (a < bb)) { s_cand[t] = bb; s_cand[x] = a; }
                }
            }
            __syncthreads();
        }
    }

    // ---- pass 4: emit top-100 (descending = from the back) --------------
    if (tid < TOPK) {
        unsigned long long key = s_cand[CAP - 1 - tid];
        float v    = __uint_as_float((unsigned)(key >> 32));
        unsigned i = ~(unsigned)key;
        if (key == 0ULL) { v = 0.0f; i = 0; }
        unsigned q = i / NC;
        unsigned c = i - q * NC;
        int o = b * TOPK + tid;
        out[o] = v;                               // scores
        out[NB * TOPK + o] = (float)c;            // labels
        const float* bx = boxes + ((size_t)(b * NQ + q)) * 4;
        float cx = bx[0], cy = bx[1], w = bx[2], h = bx[3];
        float ih = tsizes[b * 2 + 0];
        float iw = tsizes[b * 2 + 1];
        float* ob = out + 2 * NB * TOPK + (size_t)o * 4;  // boxes
        ob[0] = (cx - 0.5f * w) * iw;
        ob[1] = (cy - 0.5f * h) * ih;
        ob[2] = (cx + 0.5f * w) * iw;
        ob[3] = (cy + 0.5f * h) * ih;
    }
}

extern "C" void kernel_launch(void* const* d_in, const int* in_sizes, int n_in,
                              void* d_out, int out_size) {
    const float* logits = (const float*)d_in[0];
    const float* obj    = (const float*)d_in[1];
    const float* boxes  = (const float*)d_in[2];
    const float* unk    = (const float*)d_in[3];
    const float* ts     = (const float*)d_in[4];
    float* out = (float*)d_out;
    postprocess_kernel<<<NB, NT>>>(logits, obj, boxes, unk, ts, out);
}

// round 2
// speedup vs baseline: 1.3469x; 1.3469x over previous
#include <cuda_runtime.h>

#define NB     256
#define NQ     1000
#define NC     81
#define QCN    81000
#define TOPK   100
#define CAP    4096
#define NSAMP  2048
#define SRANK  32
#define NTA    512
#define NTB    256
#define NTC    512
#define QPB    40      // queries per B-block
#define SPLITB 25      // 25*40 = 1000 queries

// ---- global scratch (no allocs allowed) --------------------------------
__device__ float               g_w1[NB * NQ];
__device__ float               g_w2[NB * NQ];
__device__ float               g_lthr[NB * NQ];
__device__ float               g_thr[NB];
__device__ unsigned long long  g_cand[NB * CAP];
__device__ int                 g_cnt[NB];

__device__ __forceinline__ float sigf(float x) {
    return __fdividef(1.0f, 1.0f + __expf(-x));
}

// warp-aggregated push to the global per-batch candidate list
__device__ __forceinline__ void pushg(int b, unsigned long long key) {
    unsigned m = __activemask();
    int lane   = threadIdx.x & 31;
    int leader = __ffs(m) - 1;
    int rank   = __popc(m & ((1u << lane) - 1u));
    int base   = 0;
    if (lane == leader) base = atomicAdd(&g_cnt[b], __popc(m));
    base = __shfl_sync(m, base, leader);
    int pos = base + rank;
    if (pos < CAP) g_cand[b * CAP + pos] = key;  // overflow still counts -> triggers fallback
}

// warp-aggregated push to a shared-memory list (fallback path)
__device__ __forceinline__ void pushs(unsigned long long key,
                                      unsigned long long* cand, int* cnt) {
    unsigned m = __activemask();
    int lane   = threadIdx.x & 31;
    int leader = __ffs(m) - 1;
    int rank   = __popc(m & ((1u << lane) - 1u));
    int base   = 0;
    if (lane == leader) base = atomicAdd(cnt, __popc(m));
    base = __shfl_sync(m, base, leader);
    int pos = base + rank;
    if (pos < CAP) cand[pos] = key;
}

__device__ __forceinline__ float logit_thr(float te, float w1) {
    float r = __fdividef(te, w1);
    if (r >= 0.999999f) return __int_as_float(0x7f800000);  // +inf: none pass
    float lt = __logf(r) - __logf(1.0f - r) - 1e-3f;        // sigmoid^-1 with slack
    return fmaxf(lt, -20.0f);                               // keep sentinel (-1e30) excluded
}

// ======================= Kernel A: weights + threshold ===================
__global__ __launch_bounds__(NTA)
void kernelA(const float* __restrict__ logits,
             const float* __restrict__ obj,
             const float* __restrict__ unk)
{
    __shared__ unsigned s_samp[NSAMP];
    __shared__ float    s_w1[NQ];

    const int b   = blockIdx.x;
    const int tid = threadIdx.x;
    const float* lg = logits + (size_t)b * QCN;

    for (int q = tid; q < NQ; q += NTA) {
        float w  = __expf(-obj[b * NQ + q]);
        float su = sigf(unk[b * NQ + q]);
        float w1 = w * (1.0f - su);
        s_w1[q] = w1;
        g_w1[b * NQ + q] = w1;
        g_w2[b * NQ + q] = w * su;
    }
    if (tid == 0) g_cnt[b] = 0;
    __syncthreads();

    // stratified samples: 128 queries x 16 valid classes
    for (int s = tid; s < NSAMP; s += NTA) {
        int q = (s >> 4) * 7 + 3;   // 3..892
        int c = s & 15;
        float v = s_w1[q] * sigf(lg[q * NC + c]);
        s_samp[s] = __float_as_uint(v);
    }
    __syncthreads();

    // bitonic ascending sort of 2048 u32
    for (int k = 2; k <= NSAMP; k <<= 1)
        for (int j = k >> 1; j > 0; j >>= 1) {
            for (int t = tid; t < NSAMP; t += NTA) {
                int x = t ^ j;
                if (x > t) {
                    unsigned a = s_samp[t], bb = s_samp[x];
                    bool up = ((t & k) == 0);
                    if (up ? (a > bb) : (a < bb)) { s_samp[t] = bb; s_samp[x] = a; }
                }
            }
            __syncthreads();
        }

    float thr = __uint_as_float(s_samp[NSAMP - SRANK]);
    if (tid == 0) g_thr[b] = thr;
    float te = thr * 0.9999f;

    for (int q = tid; q < NQ; q += NTA) {
        g_lthr[b * NQ + q] = logit_thr(te, s_w1[q]);
        float w2 = g_w2[b * NQ + q];
        if (w2 >= te) {
            unsigned i = (unsigned)(q * NC + 80);
            pushg(b, ((unsigned long long)__float_as_uint(w2) << 32) | (~i));
        }
    }
}

// ======================= Kernel B: query-major scan ======================
__global__ __launch_bounds__(NTB)
void kernelB(const float* __restrict__ logits)
{
    const int b    = blockIdx.y;
    const int qb   = blockIdx.x * QPB;
    const int lane = threadIdx.x & 31;
    const int warp = threadIdx.x >> 5;
    const float* lg = logits + (size_t)b * QCN;

    float v0[5], v1[5], lt[5];
    int   qv[5];
#pragma unroll
    for (int j = 0; j < 5; j++) {
        int q = qb + warp + 8 * j;           // covers qb..qb+39
        qv[j] = q;
        const float* base = lg + q * NC;
        v0[j] = base[lane];                          // classes 0..31 (all valid)
        v1[j] = (lane < 28) ? base[32 + lane] : -1e30f;  // classes 32..59
        lt[j] = g_lthr[b * NQ + q];
    }
#pragma unroll
    for (int j = 0; j < 5; j++) {
        if (v0[j] >= lt[j]) {
            float p = g_w1[b * NQ + qv[j]] * sigf(v0[j]);
            unsigned i = (unsigned)(qv[j] * NC + lane);
            pushg(b, ((unsigned long long)__float_as_uint(p) << 32) | (~i));
        }
        if (v1[j] >= lt[j]) {
            float p = g_w1[b * NQ + qv[j]] * sigf(v1[j]);
            unsigned i = (unsigned)(qv[j] * NC + 32 + lane);
            pushg(b, ((unsigned long long)__float_as_uint(p) << 32) | (~i));
        }
    }
}

// ======================= Kernel C: sort + emit ===========================
__global__ __launch_bounds__(NTC)
void kernelC(const float* __restrict__ logits,
             const float* __restrict__ boxes,
             const float* __restrict__ tsizes,
             float* __restrict__ out)
{
    __shared__ unsigned long long s_cand[CAP];    // 32 KB
    __shared__ float s_w1[NQ], s_w2[NQ], s_lthr[NQ];
    __shared__ int   s_cnt;

    const int b   = blockIdx.x;
    const int tid = threadIdx.x;
    const float* lg = logits + (size_t)b * QCN;

    int n = g_cnt[b];
    if (n >= TOPK && n <= CAP) {
        for (int t = tid; t < CAP; t += NTC)
            s_cand[t] = (t < n) ? g_cand[b * CAP + t] : 0ULL;
        __syncthreads();
    } else {
        // --------- fallback: in-block rescan with threshold retry --------
        for (int q = tid; q < NQ; q += NTC) {
            s_w1[q] = g_w1[b * NQ + q];
            s_w2[q] = g_w2[b * NQ + q];
        }
        __syncthreads();
        float curthr = g_thr[b];
        for (int attempt = 0; attempt < 12; attempt++) {
            if (n < TOPK) curthr *= 0.25f; else curthr *= 4.0f;
            float te = curthr * 0.9999f;
            for (int q = tid; q < NQ; q += NTC)
                s_lthr[q] = logit_thr(te, s_w1[q]);
            if (tid == 0) s_cnt = 0;
            __syncthreads();
            for (int q = tid; q < NQ; q += NTC) {
                if (s_w2[q] >= te) {
                    unsigned i = (unsigned)(q * NC + 80);
                    pushs(((unsigned long long)__float_as_uint(s_w2[q]) << 32) | (~i),
                          s_cand, &s_cnt);
                }
            }
            for (int i = tid; i < QCN; i += NTC) {
                unsigned q = (unsigned)i / NC;
                int c = i - (int)q * NC;
                if (c < 60) {
                    float v = lg[i];
                    if (v >= s_lthr[q]) {
                        float p = s_w1[q] * sigf(v);
                        pushs(((unsigned long long)__float_as_uint(p) << 32) |
                              (~(unsigned)i), s_cand, &s_cnt);
                    }
                }
            }
            __syncthreads();
            n = s_cnt;
            if (n >= TOPK && n <= CAP) break;
            __syncthreads();
        }
        if (n > CAP) n = CAP;
        for (int t = n + tid; t < CAP; t += NTC) s_cand[t] = 0ULL;
        __syncthreads();
    }

    // bitonic ascending sort of 4096 x u64
    for (int k = 2; k <= CAP; k <<= 1)
        for (int j = k >> 1; j > 0; j >>= 1) {
            for (int t = tid; t < CAP; t += NTC) {
                int x = t ^ j;
                if (x > t) {
                    unsigned long long a = s_cand[t], bb = s_cand[x];
                    bool up = ((t & k) == 0);
                    if (up ? (a > bb) : (a < bb)) { s_cand[t] = bb; s_cand[x] = a; }
                }
            }
            __syncthreads();
        }

    // emit top-100 (descending from the back)
    if (tid < TOPK) {
        unsigned long long key = s_cand[CAP - 1 - tid];
        float v    = __uint_as_float((unsigned)(key >> 32));
        unsigned i = ~(unsigned)key;
        if (key == 0ULL) { v = 0.0f; i = 0; }
        unsigned q = i / NC;
        unsigned c = i - q * NC;
        int o = b * TOPK + tid;
        out[o] = v;                               // scores
        out[NB * TOPK + o] = (float)c;            // labels
        const float* bx = boxes + ((size_t)(b * NQ + q)) * 4;
        float cx = bx[0], cy = bx[1], w = bx[2], h = bx[3];
        float ih = tsizes[b * 2 + 0];
        float iw = tsizes[b * 2 + 1];
        float* ob = out + 2 * NB * TOPK + (size_t)o * 4;  // boxes
        ob[0] = (cx - 0.5f * w) * iw;
        ob[1] = (cy - 0.5f * h) * ih;
        ob[2] = (cx + 0.5f * w) * iw;
        ob[3] = (cy + 0.5f * h) * ih;
    }
}

extern "C" void kernel_launch(void* const* d_in, const int* in_sizes, int n_in,
                              void* d_out, int out_size) {
    const float* logits = (const float*)d_in[0];
    const float* obj    = (const float*)d_in[1];
    const float* boxes  = (const float*)d_in[2];
    const float* unk    = (const float*)d_in[3];
    const float* ts     = (const float*)d_in[4];
    float* out = (float*)d_out;

    kernelA<<<NB, NTA>>>(logits, obj, unk);
    kernelB<<<dim3(SPLITB, NB), NTB>>>(logits);
    kernelC<<<NB, NTC>>>(logits, boxes, ts, out);
}